// round 1
// baseline (speedup 1.0000x reference)
#include <cuda_runtime.h>
#include <cuda_bf16.h>
#include <math.h>

// ----------------------------------------------------------------------------
// TransformerBlock: B=2, L=2048, C=768, H=12, D=64, HIDDEN=3072, f32 baseline
// Pipeline:
//   ln1(x) -> h
//   h @ qkv_w + qkv_b -> qkv [4096,2304]
//   flash-attn(qkv) -> ctx [4096,768]
//   ctx @ proj_w + proj_b + x -> x1
//   ln2(x1) -> h
//   gelu(h @ fc1_w + fc1_b) -> ffn [4096,3072]
//   ffn @ fc2_w + fc2_b + x1 -> out
// ----------------------------------------------------------------------------

#define TOK   4096     // B*L
#define EMBED 768
#define C3    2304
#define HID   3072
#define NHEAD 12
#define HDIM  64
#define SEQ   2048

// Scratch (device globals; no allocation allowed)
__device__ float g_h  [TOK * EMBED];
__device__ float g_qkv[TOK * C3];
__device__ float g_ctx[TOK * EMBED];
__device__ float g_x1 [TOK * EMBED];
__device__ float g_ffn[TOK * HID];

// ---------------------------------------------------------------- LayerNorm
__global__ void __launch_bounds__(256) ln_kernel(const float* __restrict__ x,
                                                 const float* __restrict__ g,
                                                 const float* __restrict__ b,
                                                 float* __restrict__ out)
{
    int row = blockIdx.x;
    int tid = threadIdx.x;
    const float* xr = x + (size_t)row * EMBED;

    float v0 = xr[tid], v1 = xr[tid + 256], v2 = xr[tid + 512];
    float s  = v0 + v1 + v2;
    float s2 = v0 * v0 + v1 * v1 + v2 * v2;

    __shared__ float red[16];
    #pragma unroll
    for (int o = 16; o; o >>= 1) {
        s  += __shfl_xor_sync(0xffffffffu, s,  o);
        s2 += __shfl_xor_sync(0xffffffffu, s2, o);
    }
    int warp = tid >> 5, lane = tid & 31;
    if (lane == 0) { red[warp] = s; red[warp + 8] = s2; }
    __syncthreads();
    s = 0.f; s2 = 0.f;
    #pragma unroll
    for (int i = 0; i < 8; i++) { s += red[i]; s2 += red[i + 8]; }

    float mean = s * (1.0f / EMBED);
    float var  = s2 * (1.0f / EMBED) - mean * mean;
    float rstd = rsqrtf(var + 1e-5f);

    float* orow = out + (size_t)row * EMBED;
    orow[tid]       = (v0 - mean) * rstd * g[tid]       + b[tid];
    orow[tid + 256] = (v1 - mean) * rstd * g[tid + 256] + b[tid + 256];
    orow[tid + 512] = (v2 - mean) * rstd * g[tid + 512] + b[tid + 512];
}

// ---------------------------------------------------------------- SGEMM
// C[M,N] = A[M,K] @ W[K,N] + bias (+ optional GELU / residual)
// 128x128 block tile, BK=8, 256 threads, 8x8 per-thread (split 4+4 fragments)
__device__ __forceinline__ float gelu_f(float v)
{
    return 0.5f * v * (1.0f + erff(v * 0.70710678118654752f));
}

template <int EPI>   // 0=bias, 1=bias+gelu, 2=bias+residual
__global__ void __launch_bounds__(256) sgemm_kernel(
    const float* __restrict__ A, const float* __restrict__ W,
    const float* __restrict__ bias, const float* __restrict__ R,
    float* __restrict__ C, int M, int N, int K)
{
    __shared__ float As[8][132];   // [k][m], padded
    __shared__ float Bs[8][128];   // [k][n]

    int tid = threadIdx.x;
    int bm = blockIdx.y * 128;
    int bn = blockIdx.x * 128;

    int warp = tid >> 5, lane = tid & 31;
    int tm = (warp & 3) * 32 + (lane & 3) * 4;   // rows tm+{0..3}, tm+{16..19}
    int tn = (warp >> 2) * 64 + (lane >> 2) * 4; // cols tn+{0..3}, tn+{32..35}

    int arow = tid >> 1;
    int acol = (tid & 1) * 4;
    int brow = tid >> 5;
    int bcol = (tid & 31) << 2;

    const float* Ap = A + (size_t)(bm + arow) * K + acol;
    const float* Wp = W + (size_t)brow * N + bn + bcol;

    float acc[8][8];
    #pragma unroll
    for (int i = 0; i < 8; i++)
        #pragma unroll
        for (int j = 0; j < 8; j++) acc[i][j] = 0.f;

    float4 ar = *(const float4*)Ap;
    float4 br = *(const float4*)Wp;

    int KT = K >> 3;
    for (int kt = 0; kt < KT; kt++) {
        As[acol + 0][arow] = ar.x;
        As[acol + 1][arow] = ar.y;
        As[acol + 2][arow] = ar.z;
        As[acol + 3][arow] = ar.w;
        *(float4*)&Bs[brow][bcol] = br;
        __syncthreads();

        if (kt + 1 < KT) {
            ar = *(const float4*)(Ap + (size_t)(kt + 1) * 8);
            br = *(const float4*)(Wp + (size_t)(kt + 1) * 8 * N);
        }

        #pragma unroll
        for (int k = 0; k < 8; k++) {
            float a[8], bb[8];
            *(float4*)(a)      = *(const float4*)&As[k][tm];
            *(float4*)(a + 4)  = *(const float4*)&As[k][tm + 16];
            *(float4*)(bb)     = *(const float4*)&Bs[k][tn];
            *(float4*)(bb + 4) = *(const float4*)&Bs[k][tn + 32];
            #pragma unroll
            for (int i = 0; i < 8; i++)
                #pragma unroll
                for (int j = 0; j < 8; j++)
                    acc[i][j] += a[i] * bb[j];
        }
        __syncthreads();
    }

    // epilogue
    float4 b0 = *(const float4*)&bias[bn + tn];
    float4 b1 = *(const float4*)&bias[bn + tn + 32];
    #pragma unroll
    for (int i = 0; i < 8; i++) {
        int r = bm + tm + ((i < 4) ? i : (12 + i));
        float4 o0 = make_float4(acc[i][0] + b0.x, acc[i][1] + b0.y,
                                acc[i][2] + b0.z, acc[i][3] + b0.w);
        float4 o1 = make_float4(acc[i][4] + b1.x, acc[i][5] + b1.y,
                                acc[i][6] + b1.z, acc[i][7] + b1.w);
        if (EPI == 1) {
            o0.x = gelu_f(o0.x); o0.y = gelu_f(o0.y); o0.z = gelu_f(o0.z); o0.w = gelu_f(o0.w);
            o1.x = gelu_f(o1.x); o1.y = gelu_f(o1.y); o1.z = gelu_f(o1.z); o1.w = gelu_f(o1.w);
        }
        if (EPI == 2) {
            float4 r0 = *(const float4*)&R[(size_t)r * N + bn + tn];
            float4 r1 = *(const float4*)&R[(size_t)r * N + bn + tn + 32];
            o0.x += r0.x; o0.y += r0.y; o0.z += r0.z; o0.w += r0.w;
            o1.x += r1.x; o1.y += r1.y; o1.z += r1.z; o1.w += r1.w;
        }
        *(float4*)&C[(size_t)r * N + bn + tn]      = o0;
        *(float4*)&C[(size_t)r * N + bn + tn + 32] = o1;
    }
}

// ---------------------------------------------------------------- Attention
// Flash-style: one block per (64-query tile, head, batch). 256 threads.
// smem: sQ[64][64], sV[64][64], sP[64][64], sKt[64 dims][68 keys]
__global__ void __launch_bounds__(256) attn_kernel(const float* __restrict__ qkv,
                                                   float* __restrict__ ctx)
{
    extern __shared__ float sm[];
    float* sQ  = sm;            // 4096
    float* sV  = sm + 4096;     // 4096
    float* sP  = sm + 8192;     // 4096
    float* sKt = sm + 12288;    // 64*68 = 4352  (Kt[d][key], padded)

    int tid = threadIdx.x;
    int qt = blockIdx.x;   // 0..31
    int h  = blockIdx.y;   // 0..11
    int bb = blockIdx.z;   // 0..1

    int row0 = bb * SEQ + qt * 64;
    int qoff = h * HDIM;
    int koff = EMBED + h * HDIM;
    int voff = 2 * EMBED + h * HDIM;

    // load Q tile (scaled by 1/sqrt(64))
    #pragma unroll
    for (int it = 0; it < 4; it++) {
        int idx = tid + it * 256;
        int r = idx >> 4;
        int c = (idx & 15) << 2;
        float4 qv = *(const float4*)&qkv[(size_t)(row0 + r) * C3 + qoff + c];
        qv.x *= 0.125f; qv.y *= 0.125f; qv.z *= 0.125f; qv.w *= 0.125f;
        *(float4*)&sQ[r * 64 + c] = qv;
    }

    int r0 = (tid >> 4) << 2;   // query rows r0..r0+3
    int c0 = (tid & 15) << 2;   // key cols / out dims c0..c0+3

    float m[4], l[4], O[4][4];
    #pragma unroll
    for (int i = 0; i < 4; i++) {
        m[i] = -1e30f; l[i] = 0.f;
        #pragma unroll
        for (int j = 0; j < 4; j++) O[i][j] = 0.f;
    }

    for (int kt = 0; kt < SEQ / 64; kt++) {
        __syncthreads();  // protect smem from previous iteration's readers
        int kr0 = bb * SEQ + kt * 64;
        #pragma unroll
        for (int it = 0; it < 4; it++) {
            int idx = tid + it * 256;
            int r = idx >> 4;
            int c = (idx & 15) << 2;
            float4 kv = *(const float4*)&qkv[(size_t)(kr0 + r) * C3 + koff + c];
            sKt[(c + 0) * 68 + r] = kv.x;
            sKt[(c + 1) * 68 + r] = kv.y;
            sKt[(c + 2) * 68 + r] = kv.z;
            sKt[(c + 3) * 68 + r] = kv.w;
            float4 vv = *(const float4*)&qkv[(size_t)(kr0 + r) * C3 + voff + c];
            *(float4*)&sV[r * 64 + c] = vv;
        }
        __syncthreads();

        // S = Q @ K^T  (4x4 per thread)
        float p[4][4];
        #pragma unroll
        for (int i = 0; i < 4; i++)
            #pragma unroll
            for (int j = 0; j < 4; j++) p[i][j] = 0.f;

        #pragma unroll
        for (int d0 = 0; d0 < 64; d0 += 4) {
            float q[4][4], kk[4][4];
            #pragma unroll
            for (int rr = 0; rr < 4; rr++)
                *(float4*)q[rr] = *(const float4*)&sQ[(r0 + rr) * 64 + d0];
            #pragma unroll
            for (int dt = 0; dt < 4; dt++)
                *(float4*)kk[dt] = *(const float4*)&sKt[(d0 + dt) * 68 + c0];
            #pragma unroll
            for (int rr = 0; rr < 4; rr++)
                #pragma unroll
                for (int dt = 0; dt < 4; dt++)
                    #pragma unroll
                    for (int cc = 0; cc < 4; cc++)
                        p[rr][cc] += q[rr][dt] * kk[dt][cc];
        }

        // online softmax (row stats shared across 16-lane groups)
        #pragma unroll
        for (int rr = 0; rr < 4; rr++) {
            float mx = fmaxf(fmaxf(p[rr][0], p[rr][1]), fmaxf(p[rr][2], p[rr][3]));
            mx = fmaxf(mx, __shfl_xor_sync(0xffffffffu, mx, 1, 16));
            mx = fmaxf(mx, __shfl_xor_sync(0xffffffffu, mx, 2, 16));
            mx = fmaxf(mx, __shfl_xor_sync(0xffffffffu, mx, 4, 16));
            mx = fmaxf(mx, __shfl_xor_sync(0xffffffffu, mx, 8, 16));
            float mnew = fmaxf(m[rr], mx);
            float corr = __expf(m[rr] - mnew);
            m[rr] = mnew;
            float s = 0.f;
            #pragma unroll
            for (int cc = 0; cc < 4; cc++) {
                p[rr][cc] = __expf(p[rr][cc] - mnew);
                s += p[rr][cc];
            }
            s += __shfl_xor_sync(0xffffffffu, s, 1, 16);
            s += __shfl_xor_sync(0xffffffffu, s, 2, 16);
            s += __shfl_xor_sync(0xffffffffu, s, 4, 16);
            s += __shfl_xor_sync(0xffffffffu, s, 8, 16);
            l[rr] = l[rr] * corr + s;
            #pragma unroll
            for (int cc = 0; cc < 4; cc++) O[rr][cc] *= corr;
            *(float4*)&sP[(r0 + rr) * 64 + c0] =
                make_float4(p[rr][0], p[rr][1], p[rr][2], p[rr][3]);
        }
        __syncthreads();

        // O += P @ V
        #pragma unroll
        for (int k0 = 0; k0 < 64; k0 += 4) {
            float pp[4][4], vv[4][4];
            #pragma unroll
            for (int rr = 0; rr < 4; rr++)
                *(float4*)pp[rr] = *(const float4*)&sP[(r0 + rr) * 64 + k0];
            #pragma unroll
            for (int t = 0; t < 4; t++)
                *(float4*)vv[t] = *(const float4*)&sV[(k0 + t) * 64 + c0];
            #pragma unroll
            for (int rr = 0; rr < 4; rr++)
                #pragma unroll
                for (int t = 0; t < 4; t++)
                    #pragma unroll
                    for (int cc = 0; cc < 4; cc++)
                        O[rr][cc] += pp[rr][t] * vv[t][cc];
        }
    }

    #pragma unroll
    for (int rr = 0; rr < 4; rr++) {
        float inv = 1.0f / l[rr];
        float4 o = make_float4(O[rr][0] * inv, O[rr][1] * inv,
                               O[rr][2] * inv, O[rr][3] * inv);
        *(float4*)&ctx[(size_t)(row0 + r0 + rr) * EMBED + h * HDIM + c0] = o;
    }
}

// ---------------------------------------------------------------- launch
extern "C" void kernel_launch(void* const* d_in, const int* in_sizes, int n_in,
                              void* d_out, int out_size)
{
    const float* x      = (const float*)d_in[0];
    const float* ln1_g  = (const float*)d_in[1];
    const float* ln1_b  = (const float*)d_in[2];
    const float* qkv_w  = (const float*)d_in[3];
    const float* qkv_b  = (const float*)d_in[4];
    const float* proj_w = (const float*)d_in[5];
    const float* proj_b = (const float*)d_in[6];
    const float* ln2_g  = (const float*)d_in[7];
    const float* ln2_b  = (const float*)d_in[8];
    const float* fc1_w  = (const float*)d_in[9];
    const float* fc1_b  = (const float*)d_in[10];
    const float* fc2_w  = (const float*)d_in[11];
    const float* fc2_b  = (const float*)d_in[12];
    float* out = (float*)d_out;

    float *h, *qkvb, *ctx, *x1, *ffn;
    cudaGetSymbolAddress((void**)&h,    g_h);
    cudaGetSymbolAddress((void**)&qkvb, g_qkv);
    cudaGetSymbolAddress((void**)&ctx,  g_ctx);
    cudaGetSymbolAddress((void**)&x1,   g_x1);
    cudaGetSymbolAddress((void**)&ffn,  g_ffn);

    const int ATTN_SMEM = (3 * 4096 + 64 * 68) * sizeof(float);  // 66560 B
    cudaFuncSetAttribute(attn_kernel,
                         cudaFuncAttributeMaxDynamicSharedMemorySize, ATTN_SMEM);

    // 1. LN1
    ln_kernel<<<TOK, 256>>>(x, ln1_g, ln1_b, h);
    // 2. QKV GEMM
    sgemm_kernel<0><<<dim3(C3 / 128, TOK / 128), 256>>>(
        h, qkv_w, qkv_b, nullptr, qkvb, TOK, C3, EMBED);
    // 3. attention
    attn_kernel<<<dim3(SEQ / 64, NHEAD, 2), 256, ATTN_SMEM>>>(qkvb, ctx);
    // 4. proj GEMM + residual(x)
    sgemm_kernel<2><<<dim3(EMBED / 128, TOK / 128), 256>>>(
        ctx, proj_w, proj_b, x, x1, TOK, EMBED, EMBED);
    // 5. LN2
    ln_kernel<<<TOK, 256>>>(x1, ln2_g, ln2_b, h);
    // 6. FC1 + GELU
    sgemm_kernel<1><<<dim3(HID / 128, TOK / 128), 256>>>(
        h, fc1_w, fc1_b, nullptr, ffn, TOK, HID, EMBED);
    // 7. FC2 + residual(x1) -> out
    sgemm_kernel<2><<<dim3(EMBED / 128, TOK / 128), 256>>>(
        ffn, fc2_w, fc2_b, x1, out, TOK, EMBED, HID);
}

// round 3
// speedup vs baseline: 1.4844x; 1.4844x over previous
#include <cuda_runtime.h>
#include <cuda_bf16.h>
#include <math.h>
#include <stdint.h>

// ----------------------------------------------------------------------------
// TransformerBlock on GB300 (sm_103, baseline-PTX features only):
//   GEMMs: mma.sync.m16n8k16 bf16 with hi/lo split (3 terms ~ f32 accuracy),
//          cp.async double-buffered 128x128x64 tiles, SW128 swizzle + ldmatrix.
//   Attention: f32 flash kernel (tensorize next round).
// ----------------------------------------------------------------------------

#define TOK   4096
#define EMBED 768
#define C3    2304
#define HID   3072
#define NHEAD 12
#define HDIM  64
#define SEQ   2048

__device__ float g_qkv[TOK * C3];
__device__ float g_x1 [TOK * EMBED];
__device__ __nv_bfloat16 g_hhi[TOK * EMBED], g_hlo[TOK * EMBED];
__device__ __nv_bfloat16 g_chi[TOK * EMBED], g_clo[TOK * EMBED];
__device__ __nv_bfloat16 g_fhi[TOK * HID],   g_flo[TOK * HID];
__device__ __nv_bfloat16 g_w0h[C3 * EMBED],  g_w0l[C3 * EMBED];
__device__ __nv_bfloat16 g_w1h[EMBED*EMBED], g_w1l[EMBED*EMBED];
__device__ __nv_bfloat16 g_w2h[HID * EMBED], g_w2l[HID * EMBED];
__device__ __nv_bfloat16 g_w3h[EMBED * HID], g_w3l[EMBED * HID];

__device__ __forceinline__ uint32_t smem_u32(const void* p) {
    uint32_t a;
    asm("{ .reg .u64 t; cvta.to.shared.u64 t, %1; cvt.u32.u64 %0, t; }"
        : "=r"(a) : "l"(p));
    return a;
}
__device__ __forceinline__ void split_bf16(float v, __nv_bfloat16& hi, __nv_bfloat16& lo) {
    hi = __float2bfloat16(v);
    lo = __float2bfloat16(v - __bfloat162float(hi));
}
__device__ __forceinline__ float gelu_f(float v) {
    return 0.5f * v * (1.0f + erff(v * 0.70710678118654752f));
}
__device__ __forceinline__ void cp16(uint32_t dst, const void* src) {
    asm volatile("cp.async.cg.shared.global [%0], [%1], 16;" :: "r"(dst), "l"(src));
}
#define CP_COMMIT()  asm volatile("cp.async.commit_group;" ::: "memory")
#define CP_WAIT_1()  asm volatile("cp.async.wait_group 1;" ::: "memory")
#define CP_WAIT_0()  asm volatile("cp.async.wait_group 0;" ::: "memory")

__device__ __forceinline__ void ldsm4(uint32_t a, uint32_t* r) {
    asm volatile("ldmatrix.sync.aligned.m8n8.x4.shared.b16 {%0,%1,%2,%3}, [%4];"
                 : "=r"(r[0]), "=r"(r[1]), "=r"(r[2]), "=r"(r[3]) : "r"(a));
}
__device__ __forceinline__ void mma16816(float* c, const uint32_t* a,
                                         uint32_t b0, uint32_t b1) {
    asm volatile(
        "mma.sync.aligned.m16n8k16.row.col.f32.bf16.bf16.f32 "
        "{%0,%1,%2,%3}, {%4,%5,%6,%7}, {%8,%9}, {%0,%1,%2,%3};"
        : "+f"(c[0]), "+f"(c[1]), "+f"(c[2]), "+f"(c[3])
        : "r"(a[0]), "r"(a[1]), "r"(a[2]), "r"(a[3]), "r"(b0), "r"(b1));
}

// ---------------- weight transpose + bf16 split: W[K,N] -> T[N,K] -------------
__global__ void __launch_bounds__(256) transpose_split(
    const float* __restrict__ W, __nv_bfloat16* __restrict__ Th,
    __nv_bfloat16* __restrict__ Tl, int K, int N)
{
    __shared__ float t[32][33];
    int n0 = blockIdx.x * 32, k0 = blockIdx.y * 32;
    int tx = threadIdx.x & 31, ty = threadIdx.x >> 5;
    #pragma unroll
    for (int j = 0; j < 4; j++)
        t[ty + j * 8][tx] = W[(size_t)(k0 + ty + j * 8) * N + n0 + tx];
    __syncthreads();
    #pragma unroll
    for (int j = 0; j < 4; j++) {
        int n = n0 + ty + j * 8;
        float v = t[tx][ty + j * 8];
        __nv_bfloat16 h, l; split_bf16(v, h, l);
        Th[(size_t)n * K + k0 + tx] = h;
        Tl[(size_t)n * K + k0 + tx] = l;
    }
}

// ---------------- LayerNorm -> bf16 hi/lo --------------------------------------
__global__ void __launch_bounds__(256) ln_kernel(const float* __restrict__ x,
                                                 const float* __restrict__ g,
                                                 const float* __restrict__ b,
                                                 __nv_bfloat16* __restrict__ ohi,
                                                 __nv_bfloat16* __restrict__ olo)
{
    int row = blockIdx.x;
    int tid = threadIdx.x;
    const float* xr = x + (size_t)row * EMBED;

    float v0 = xr[tid], v1 = xr[tid + 256], v2 = xr[tid + 512];
    float s  = v0 + v1 + v2;
    float s2 = v0 * v0 + v1 * v1 + v2 * v2;

    __shared__ float red[16];
    #pragma unroll
    for (int o = 16; o; o >>= 1) {
        s  += __shfl_xor_sync(0xffffffffu, s,  o);
        s2 += __shfl_xor_sync(0xffffffffu, s2, o);
    }
    int warp = tid >> 5, lane = tid & 31;
    if (lane == 0) { red[warp] = s; red[warp + 8] = s2; }
    __syncthreads();
    s = 0.f; s2 = 0.f;
    #pragma unroll
    for (int i = 0; i < 8; i++) { s += red[i]; s2 += red[i + 8]; }

    float mean = s * (1.0f / EMBED);
    float var  = s2 * (1.0f / EMBED) - mean * mean;
    float rstd = rsqrtf(var + 1e-5f);

    size_t base = (size_t)row * EMBED;
    #pragma unroll
    for (int j = 0; j < 3; j++) {
        int c = tid + j * 256;
        float v = (j == 0 ? v0 : (j == 1 ? v1 : v2));
        float y = (v - mean) * rstd * g[c] + b[c];
        __nv_bfloat16 h, l; split_bf16(y, h, l);
        ohi[base + c] = h;
        olo[base + c] = l;
    }
}

// ---------------- bf16 split MMA GEMM ------------------------------------------
#define STG_TILE  16384
#define STG_BYTES (4 * STG_TILE)
#define GEMM_SMEM (2 * STG_BYTES)   // 131072

__device__ __forceinline__ void cp_tile(const __nv_bfloat16* __restrict__ src,
                                        int ldK, uint32_t dst, int kt, int tid)
{
    const char* base = (const char*)src + (size_t)kt * 128;
    #pragma unroll
    for (int i = 0; i < 4; i++) {
        int idx = tid + i * 256;
        int r = idx >> 3;
        int c = idx & 7;
        cp16(dst + (r << 7) + ((c ^ (r & 7)) << 4),
             base + (size_t)r * ldK * 2 + c * 16);
    }
}

__device__ __forceinline__ uint32_t frag_addr(uint32_t base, int row0, int k16, int lane)
{
    int sub = lane >> 3, i = lane & 7;
    int row = row0 + ((sub & 1) << 3) + i;
    int chunk = (k16 << 1) + (sub >> 1);
    return base + (row << 7) + ((chunk ^ (row & 7)) << 4);
}

__device__ __forceinline__ void compute_stage(uint32_t sb, int m0, int n0,
                                              int lane, float acc[4][4][4])
{
    uint32_t aAh = sb, aAl = sb + STG_TILE, aBh = sb + 2 * STG_TILE, aBl = sb + 3 * STG_TILE;
    #pragma unroll
    for (int k16 = 0; k16 < 4; k16++) {
        uint32_t ah[4][4], al[4][4], bh[2][4], bl[2][4];
        #pragma unroll
        for (int mi = 0; mi < 4; mi++) {
            ldsm4(frag_addr(aAh, m0 + mi * 16, k16, lane), ah[mi]);
            ldsm4(frag_addr(aAl, m0 + mi * 16, k16, lane), al[mi]);
        }
        #pragma unroll
        for (int g = 0; g < 2; g++) {
            ldsm4(frag_addr(aBh, n0 + g * 16, k16, lane), bh[g]);
            ldsm4(frag_addr(aBl, n0 + g * 16, k16, lane), bl[g]);
        }
        #pragma unroll
        for (int mi = 0; mi < 4; mi++) {
            #pragma unroll
            for (int g = 0; g < 2; g++) {
                mma16816(acc[mi][g * 2 + 0], ah[mi], bh[g][0], bh[g][2]);
                mma16816(acc[mi][g * 2 + 1], ah[mi], bh[g][1], bh[g][3]);
                mma16816(acc[mi][g * 2 + 0], ah[mi], bl[g][0], bl[g][2]);
                mma16816(acc[mi][g * 2 + 1], ah[mi], bl[g][1], bl[g][3]);
                mma16816(acc[mi][g * 2 + 0], al[mi], bh[g][0], bh[g][2]);
                mma16816(acc[mi][g * 2 + 1], al[mi], bh[g][1], bh[g][3]);
            }
        }
    }
}

template <int EPI>   // 0=bias->f32, 1=bias+gelu->bf16 hi/lo, 2=bias+residual->f32
__global__ void __launch_bounds__(256, 1) mma_gemm(
    const __nv_bfloat16* __restrict__ Ahi, const __nv_bfloat16* __restrict__ Alo,
    const __nv_bfloat16* __restrict__ Bhi, const __nv_bfloat16* __restrict__ Blo,
    const float* __restrict__ bias, const float* __restrict__ R,
    float* __restrict__ Cf, __nv_bfloat16* __restrict__ Chi,
    __nv_bfloat16* __restrict__ Clo, int M, int N, int K)
{
    extern __shared__ __align__(128) char sm[];
    uint32_t smb = smem_u32(sm);
    int tid = threadIdx.x, lane = tid & 31, wid = tid >> 5;
    int bm = blockIdx.y * 128, bn = blockIdx.x * 128;
    int m0 = (wid & 1) * 64, n0 = (wid >> 1) * 32;

    const __nv_bfloat16* Ah = Ahi + (size_t)bm * K;
    const __nv_bfloat16* Al = Alo + (size_t)bm * K;
    const __nv_bfloat16* Bh = Bhi + (size_t)bn * K;
    const __nv_bfloat16* Bl = Blo + (size_t)bn * K;

    float acc[4][4][4];
    #pragma unroll
    for (int a = 0; a < 4; a++)
        #pragma unroll
        for (int b = 0; b < 4; b++)
            #pragma unroll
            for (int c = 0; c < 4; c++) acc[a][b][c] = 0.f;

    int KT = K >> 6;

    cp_tile(Ah, K, smb,                 0, tid);
    cp_tile(Al, K, smb +     STG_TILE,  0, tid);
    cp_tile(Bh, K, smb + 2 * STG_TILE,  0, tid);
    cp_tile(Bl, K, smb + 3 * STG_TILE,  0, tid);
    CP_COMMIT();

    for (int kt = 0; kt < KT; kt++) {
        if (kt + 1 < KT) {
            uint32_t sN = smb + ((kt + 1) & 1) * STG_BYTES;
            cp_tile(Ah, K, sN,                 kt + 1, tid);
            cp_tile(Al, K, sN +     STG_TILE,  kt + 1, tid);
            cp_tile(Bh, K, sN + 2 * STG_TILE,  kt + 1, tid);
            cp_tile(Bl, K, sN + 3 * STG_TILE,  kt + 1, tid);
            CP_COMMIT();
            CP_WAIT_1();
        } else {
            CP_WAIT_0();
        }
        __syncthreads();
        compute_stage(smb + (kt & 1) * STG_BYTES, m0, n0, lane, acc);
        __syncthreads();
    }

    int r_lo = lane >> 2;
    int c2   = (lane & 3) << 1;
    #pragma unroll
    for (int mi = 0; mi < 4; mi++) {
        #pragma unroll
        for (int nj = 0; nj < 4; nj++) {
            int gr = bm + m0 + mi * 16 + r_lo;
            int gc = bn + n0 + nj * 8 + c2;
            float2 bv = *(const float2*)&bias[gc];
            float v0 = acc[mi][nj][0] + bv.x;
            float v1 = acc[mi][nj][1] + bv.y;
            float v2 = acc[mi][nj][2] + bv.x;
            float v3 = acc[mi][nj][3] + bv.y;
            size_t go0 = (size_t)gr * N + gc;
            size_t go1 = (size_t)(gr + 8) * N + gc;
            if (EPI == 0) {
                *(float2*)&Cf[go0] = make_float2(v0, v1);
                *(float2*)&Cf[go1] = make_float2(v2, v3);
            } else if (EPI == 1) {
                float g0 = gelu_f(v0), g1 = gelu_f(v1);
                float g2 = gelu_f(v2), g3 = gelu_f(v3);
                __nv_bfloat16 h0,l0,h1,l1,h2,l2,h3,l3;
                split_bf16(g0,h0,l0); split_bf16(g1,h1,l1);
                split_bf16(g2,h2,l2); split_bf16(g3,h3,l3);
                *(__nv_bfloat162*)&Chi[go0] = __halves2bfloat162(h0, h1);
                *(__nv_bfloat162*)&Clo[go0] = __halves2bfloat162(l0, l1);
                *(__nv_bfloat162*)&Chi[go1] = __halves2bfloat162(h2, h3);
                *(__nv_bfloat162*)&Clo[go1] = __halves2bfloat162(l2, l3);
            } else {
                float2 r0 = *(const float2*)&R[go0];
                float2 r1 = *(const float2*)&R[go1];
                *(float2*)&Cf[go0] = make_float2(v0 + r0.x, v1 + r0.y);
                *(float2*)&Cf[go1] = make_float2(v2 + r1.x, v3 + r1.y);
            }
        }
    }
}

// ---------------- Attention (f32 flash) ----------------------------------------
__global__ void __launch_bounds__(256) attn_kernel(const float* __restrict__ qkv,
                                                   __nv_bfloat16* __restrict__ chi,
                                                   __nv_bfloat16* __restrict__ clo)
{
    extern __shared__ float smf[];
    float* sQ  = smf;
    float* sV  = smf + 4096;
    float* sP  = smf + 8192;
    float* sKt = smf + 12288;

    int tid = threadIdx.x;
    int qt = blockIdx.x, h = blockIdx.y, bb = blockIdx.z;

    int row0 = bb * SEQ + qt * 64;
    int qoff = h * HDIM;
    int koff = EMBED + h * HDIM;
    int voff = 2 * EMBED + h * HDIM;

    #pragma unroll
    for (int it = 0; it < 4; it++) {
        int idx = tid + it * 256;
        int r = idx >> 4;
        int c = (idx & 15) << 2;
        float4 qv = *(const float4*)&qkv[(size_t)(row0 + r) * C3 + qoff + c];
        qv.x *= 0.125f; qv.y *= 0.125f; qv.z *= 0.125f; qv.w *= 0.125f;
        *(float4*)&sQ[r * 64 + c] = qv;
    }

    int r0 = (tid >> 4) << 2;
    int c0 = (tid & 15) << 2;

    float m[4], l[4], O[4][4];
    #pragma unroll
    for (int i = 0; i < 4; i++) {
        m[i] = -1e30f; l[i] = 0.f;
        #pragma unroll
        for (int j = 0; j < 4; j++) O[i][j] = 0.f;
    }

    for (int kt = 0; kt < SEQ / 64; kt++) {
        __syncthreads();
        int kr0 = bb * SEQ + kt * 64;
        #pragma unroll
        for (int it = 0; it < 4; it++) {
            int idx = tid + it * 256;
            int r = idx >> 4;
            int c = (idx & 15) << 2;
            float4 kv = *(const float4*)&qkv[(size_t)(kr0 + r) * C3 + koff + c];
            sKt[(c + 0) * 68 + r] = kv.x;
            sKt[(c + 1) * 68 + r] = kv.y;
            sKt[(c + 2) * 68 + r] = kv.z;
            sKt[(c + 3) * 68 + r] = kv.w;
            float4 vv = *(const float4*)&qkv[(size_t)(kr0 + r) * C3 + voff + c];
            *(float4*)&sV[r * 64 + c] = vv;
        }
        __syncthreads();

        float p[4][4];
        #pragma unroll
        for (int i = 0; i < 4; i++)
            #pragma unroll
            for (int j = 0; j < 4; j++) p[i][j] = 0.f;

        #pragma unroll
        for (int d0 = 0; d0 < 64; d0 += 4) {
            float q[4][4], kk[4][4];
            #pragma unroll
            for (int rr = 0; rr < 4; rr++)
                *(float4*)q[rr] = *(const float4*)&sQ[(r0 + rr) * 64 + d0];
            #pragma unroll
            for (int dt = 0; dt < 4; dt++)
                *(float4*)kk[dt] = *(const float4*)&sKt[(d0 + dt) * 68 + c0];
            #pragma unroll
            for (int rr = 0; rr < 4; rr++)
                #pragma unroll
                for (int dt = 0; dt < 4; dt++)
                    #pragma unroll
                    for (int cc = 0; cc < 4; cc++)
                        p[rr][cc] += q[rr][dt] * kk[dt][cc];
        }

        #pragma unroll
        for (int rr = 0; rr < 4; rr++) {
            float mx = fmaxf(fmaxf(p[rr][0], p[rr][1]), fmaxf(p[rr][2], p[rr][3]));
            mx = fmaxf(mx, __shfl_xor_sync(0xffffffffu, mx, 1, 16));
            mx = fmaxf(mx, __shfl_xor_sync(0xffffffffu, mx, 2, 16));
            mx = fmaxf(mx, __shfl_xor_sync(0xffffffffu, mx, 4, 16));
            mx = fmaxf(mx, __shfl_xor_sync(0xffffffffu, mx, 8, 16));
            float mnew = fmaxf(m[rr], mx);
            float corr = __expf(m[rr] - mnew);
            m[rr] = mnew;
            float s = 0.f;
            #pragma unroll
            for (int cc = 0; cc < 4; cc++) {
                p[rr][cc] = __expf(p[rr][cc] - mnew);
                s += p[rr][cc];
            }
            s += __shfl_xor_sync(0xffffffffu, s, 1, 16);
            s += __shfl_xor_sync(0xffffffffu, s, 2, 16);
            s += __shfl_xor_sync(0xffffffffu, s, 4, 16);
            s += __shfl_xor_sync(0xffffffffu, s, 8, 16);
            l[rr] = l[rr] * corr + s;
            #pragma unroll
            for (int cc = 0; cc < 4; cc++) O[rr][cc] *= corr;
            *(float4*)&sP[(r0 + rr) * 64 + c0] =
                make_float4(p[rr][0], p[rr][1], p[rr][2], p[rr][3]);
        }
        __syncthreads();

        #pragma unroll
        for (int k0 = 0; k0 < 64; k0 += 4) {
            float pp[4][4], vv[4][4];
            #pragma unroll
            for (int rr = 0; rr < 4; rr++)
                *(float4*)pp[rr] = *(const float4*)&sP[(r0 + rr) * 64 + k0];
            #pragma unroll
            for (int t = 0; t < 4; t++)
                *(float4*)vv[t] = *(const float4*)&sV[(k0 + t) * 64 + c0];
            #pragma unroll
            for (int rr = 0; rr < 4; rr++)
                #pragma unroll
                for (int t = 0; t < 4; t++)
                    #pragma unroll
                    for (int cc = 0; cc < 4; cc++)
                        O[rr][cc] += pp[rr][t] * vv[t][cc];
        }
    }

    #pragma unroll
    for (int rr = 0; rr < 4; rr++) {
        float inv = 1.0f / l[rr];
        size_t go = (size_t)(row0 + r0 + rr) * EMBED + h * HDIM + c0;
        #pragma unroll
        for (int cc = 0; cc < 4; cc++) {
            float v = O[rr][cc] * inv;
            __nv_bfloat16 hh, ll; split_bf16(v, hh, ll);
            chi[go + cc] = hh;
            clo[go + cc] = ll;
        }
    }
}

// ---------------- launch --------------------------------------------------------
extern "C" void kernel_launch(void* const* d_in, const int* in_sizes, int n_in,
                              void* d_out, int out_size)
{
    const float* x      = (const float*)d_in[0];
    const float* ln1_g  = (const float*)d_in[1];
    const float* ln1_b  = (const float*)d_in[2];
    const float* qkv_w  = (const float*)d_in[3];
    const float* qkv_b  = (const float*)d_in[4];
    const float* proj_w = (const float*)d_in[5];
    const float* proj_b = (const float*)d_in[6];
    const float* ln2_g  = (const float*)d_in[7];
    const float* ln2_b  = (const float*)d_in[8];
    const float* fc1_w  = (const float*)d_in[9];
    const float* fc1_b  = (const float*)d_in[10];
    const float* fc2_w  = (const float*)d_in[11];
    const float* fc2_b  = (const float*)d_in[12];
    float* out = (float*)d_out;

    float *qkvb, *x1;
    __nv_bfloat16 *hhi, *hlo, *chi, *clo, *fhi, *flo;
    __nv_bfloat16 *w0h, *w0l, *w1h, *w1l, *w2h, *w2l, *w3h, *w3l;
    cudaGetSymbolAddress((void**)&qkvb, g_qkv);
    cudaGetSymbolAddress((void**)&x1,   g_x1);
    cudaGetSymbolAddress((void**)&hhi,  g_hhi);  cudaGetSymbolAddress((void**)&hlo, g_hlo);
    cudaGetSymbolAddress((void**)&chi,  g_chi);  cudaGetSymbolAddress((void**)&clo, g_clo);
    cudaGetSymbolAddress((void**)&fhi,  g_fhi);  cudaGetSymbolAddress((void**)&flo, g_flo);
    cudaGetSymbolAddress((void**)&w0h,  g_w0h);  cudaGetSymbolAddress((void**)&w0l, g_w0l);
    cudaGetSymbolAddress((void**)&w1h,  g_w1h);  cudaGetSymbolAddress((void**)&w1l, g_w1l);
    cudaGetSymbolAddress((void**)&w2h,  g_w2h);  cudaGetSymbolAddress((void**)&w2l, g_w2l);
    cudaGetSymbolAddress((void**)&w3h,  g_w3h);  cudaGetSymbolAddress((void**)&w3l, g_w3l);

    const int ATTN_SMEM = (3 * 4096 + 64 * 68) * sizeof(float);
    cudaFuncSetAttribute(attn_kernel,
                         cudaFuncAttributeMaxDynamicSharedMemorySize, ATTN_SMEM);
    cudaFuncSetAttribute(mma_gemm<0>, cudaFuncAttributeMaxDynamicSharedMemorySize, GEMM_SMEM);
    cudaFuncSetAttribute(mma_gemm<1>, cudaFuncAttributeMaxDynamicSharedMemorySize, GEMM_SMEM);
    cudaFuncSetAttribute(mma_gemm<2>, cudaFuncAttributeMaxDynamicSharedMemorySize, GEMM_SMEM);

    transpose_split<<<dim3(C3 / 32,    EMBED / 32), 256>>>(qkv_w,  w0h, w0l, EMBED, C3);
    transpose_split<<<dim3(EMBED / 32, EMBED / 32), 256>>>(proj_w, w1h, w1l, EMBED, EMBED);
    transpose_split<<<dim3(HID / 32,   EMBED / 32), 256>>>(fc1_w,  w2h, w2l, EMBED, HID);
    transpose_split<<<dim3(EMBED / 32, HID / 32),   256>>>(fc2_w,  w3h, w3l, HID, EMBED);

    ln_kernel<<<TOK, 256>>>(x, ln1_g, ln1_b, hhi, hlo);
    mma_gemm<0><<<dim3(C3 / 128, TOK / 128), 256, GEMM_SMEM>>>(
        hhi, hlo, w0h, w0l, qkv_b, nullptr, qkvb, nullptr, nullptr,
        TOK, C3, EMBED);
    attn_kernel<<<dim3(SEQ / 64, NHEAD, 2), 256, ATTN_SMEM>>>(qkvb, chi, clo);
    mma_gemm<2><<<dim3(EMBED / 128, TOK / 128), 256, GEMM_SMEM>>>(
        chi, clo, w1h, w1l, proj_b, x, x1, nullptr, nullptr,
        TOK, EMBED, EMBED);
    ln_kernel<<<TOK, 256>>>(x1, ln2_g, ln2_b, hhi, hlo);
    mma_gemm<1><<<dim3(HID / 128, TOK / 128), 256, GEMM_SMEM>>>(
        hhi, hlo, w2h, w2l, fc1_b, nullptr, nullptr, fhi, flo,
        TOK, HID, EMBED);
    mma_gemm<2><<<dim3(EMBED / 128, TOK / 128), 256, GEMM_SMEM>>>(
        fhi, flo, w3h, w3l, fc2_b, x1, out, nullptr, nullptr,
        TOK, EMBED, HID);
}

// round 4
// speedup vs baseline: 2.2944x; 1.5456x over previous
#include <cuda_runtime.h>
#include <cuda_bf16.h>
#include <math.h>
#include <stdint.h>

// ----------------------------------------------------------------------------
// TransformerBlock (sm_103 baseline-PTX): all GEMMs + attention on mma.sync bf16
// with hi/lo split (3 terms ~ f32 accuracy). cp.async pipelines throughout.
// ----------------------------------------------------------------------------

#define TOK   4096
#define EMBED 768
#define C3    2304
#define HID   3072
#define NHEAD 12
#define HDIM  64
#define SEQ   2048

__device__ float g_x1 [TOK * EMBED];
__device__ __nv_bfloat16 g_qkvh[TOK * C3],   g_qkvl[TOK * C3];
__device__ __nv_bfloat16 g_hhi[TOK * EMBED], g_hlo[TOK * EMBED];
__device__ __nv_bfloat16 g_chi[TOK * EMBED], g_clo[TOK * EMBED];
__device__ __nv_bfloat16 g_fhi[TOK * HID],   g_flo[TOK * HID];
__device__ __nv_bfloat16 g_w0h[C3 * EMBED],  g_w0l[C3 * EMBED];
__device__ __nv_bfloat16 g_w1h[EMBED*EMBED], g_w1l[EMBED*EMBED];
__device__ __nv_bfloat16 g_w2h[HID * EMBED], g_w2l[HID * EMBED];
__device__ __nv_bfloat16 g_w3h[EMBED * HID], g_w3l[EMBED * HID];

// ---------------- primitives ---------------------------------------------------
__device__ __forceinline__ uint32_t smem_u32(const void* p) {
    uint32_t a;
    asm("{ .reg .u64 t; cvta.to.shared.u64 t, %1; cvt.u32.u64 %0, t; }"
        : "=r"(a) : "l"(p));
    return a;
}
__device__ __forceinline__ void split_bf16(float v, __nv_bfloat16& hi, __nv_bfloat16& lo) {
    hi = __float2bfloat16(v);
    lo = __float2bfloat16(v - __bfloat162float(hi));
}
__device__ __forceinline__ float gelu_f(float v) {
    return 0.5f * v * (1.0f + erff(v * 0.70710678118654752f));
}
__device__ __forceinline__ void cp16(uint32_t dst, const void* src) {
    asm volatile("cp.async.cg.shared.global [%0], [%1], 16;" :: "r"(dst), "l"(src));
}
#define CP_COMMIT()  asm volatile("cp.async.commit_group;" ::: "memory")
#define CP_WAIT_2()  asm volatile("cp.async.wait_group 2;" ::: "memory")
#define CP_WAIT_1()  asm volatile("cp.async.wait_group 1;" ::: "memory")
#define CP_WAIT_0()  asm volatile("cp.async.wait_group 0;" ::: "memory")

__device__ __forceinline__ void ldsm4(uint32_t a, uint32_t* r) {
    asm volatile("ldmatrix.sync.aligned.m8n8.x4.shared.b16 {%0,%1,%2,%3}, [%4];"
                 : "=r"(r[0]), "=r"(r[1]), "=r"(r[2]), "=r"(r[3]) : "r"(a));
}
__device__ __forceinline__ void ldsm4t(uint32_t a, uint32_t* r) {
    asm volatile("ldmatrix.sync.aligned.m8n8.x4.trans.shared.b16 {%0,%1,%2,%3}, [%4];"
                 : "=r"(r[0]), "=r"(r[1]), "=r"(r[2]), "=r"(r[3]) : "r"(a));
}
__device__ __forceinline__ void mma16816(float* c, const uint32_t* a,
                                         uint32_t b0, uint32_t b1) {
    asm volatile(
        "mma.sync.aligned.m16n8k16.row.col.f32.bf16.bf16.f32 "
        "{%0,%1,%2,%3}, {%4,%5,%6,%7}, {%8,%9}, {%0,%1,%2,%3};"
        : "+f"(c[0]), "+f"(c[1]), "+f"(c[2]), "+f"(c[3])
        : "r"(a[0]), "r"(a[1]), "r"(a[2]), "r"(a[3]), "r"(b0), "r"(b1));
}

// universal 128B-line swizzle (byte offsets, 16B granularity)
__device__ __forceinline__ uint32_t sw128b(uint32_t off) {
    return off ^ (((off >> 7) & 7) << 4);
}
// fragment address for tiles with 128B rows (row-major, k16 selects 32B pair)
__device__ __forceinline__ uint32_t frag_addr(uint32_t base, int row0, int k16, int lane)
{
    int sub = lane >> 3, i = lane & 7;
    int row = row0 + ((sub & 1) << 3) + i;
    int chunk = (k16 << 1) + (sub >> 1);
    return base + sw128b((row << 7) + (chunk << 4));
}
// fragment address for tiles with 64B rows (BK=32)
__device__ __forceinline__ uint32_t frag_a32(uint32_t base, int row0, int k16, int lane)
{
    int sub = lane >> 3, i = lane & 7;
    int row = row0 + ((sub & 1) << 3) + i;
    int chunk = (k16 << 1) + (sub >> 1);
    return base + sw128b((row << 6) + (chunk << 4));
}
// V fragment (B, col) via ldmatrix.trans on V[key][dim] (128B rows)
__device__ __forceinline__ uint32_t vaddr(uint32_t base, int k0, int d0, int lane)
{
    int sub = lane >> 3, i = lane & 7;
    int key = k0 + ((sub >> 1) << 3) + i;
    int dim = d0 + ((sub & 1) << 3);
    return base + sw128b((key << 7) + (dim << 1));
}

// ---------------- weight transpose + split ------------------------------------
__global__ void __launch_bounds__(256) transpose_split(
    const float* __restrict__ W, __nv_bfloat16* __restrict__ Th,
    __nv_bfloat16* __restrict__ Tl, int K, int N)
{
    __shared__ float t[32][33];
    int n0 = blockIdx.x * 32, k0 = blockIdx.y * 32;
    int tx = threadIdx.x & 31, ty = threadIdx.x >> 5;
    #pragma unroll
    for (int j = 0; j < 4; j++)
        t[ty + j * 8][tx] = W[(size_t)(k0 + ty + j * 8) * N + n0 + tx];
    __syncthreads();
    #pragma unroll
    for (int j = 0; j < 4; j++) {
        int n = n0 + ty + j * 8;
        float v = t[tx][ty + j * 8];
        __nv_bfloat16 h, l; split_bf16(v, h, l);
        Th[(size_t)n * K + k0 + tx] = h;
        Tl[(size_t)n * K + k0 + tx] = l;
    }
}

// ---------------- LayerNorm -> bf16 hi/lo --------------------------------------
__global__ void __launch_bounds__(256) ln_kernel(const float* __restrict__ x,
                                                 const float* __restrict__ g,
                                                 const float* __restrict__ b,
                                                 __nv_bfloat16* __restrict__ ohi,
                                                 __nv_bfloat16* __restrict__ olo)
{
    int row = blockIdx.x;
    int tid = threadIdx.x;
    const float* xr = x + (size_t)row * EMBED;

    float v0 = xr[tid], v1 = xr[tid + 256], v2 = xr[tid + 512];
    float s  = v0 + v1 + v2;
    float s2 = v0 * v0 + v1 * v1 + v2 * v2;

    __shared__ float red[16];
    #pragma unroll
    for (int o = 16; o; o >>= 1) {
        s  += __shfl_xor_sync(0xffffffffu, s,  o);
        s2 += __shfl_xor_sync(0xffffffffu, s2, o);
    }
    int warp = tid >> 5, lane = tid & 31;
    if (lane == 0) { red[warp] = s; red[warp + 8] = s2; }
    __syncthreads();
    s = 0.f; s2 = 0.f;
    #pragma unroll
    for (int i = 0; i < 8; i++) { s += red[i]; s2 += red[i + 8]; }

    float mean = s * (1.0f / EMBED);
    float var  = s2 * (1.0f / EMBED) - mean * mean;
    float rstd = rsqrtf(var + 1e-5f);

    size_t base = (size_t)row * EMBED;
    #pragma unroll
    for (int j = 0; j < 3; j++) {
        int c = tid + j * 256;
        float v = (j == 0 ? v0 : (j == 1 ? v1 : v2));
        float y = (v - mean) * rstd * g[c] + b[c];
        __nv_bfloat16 h, l; split_bf16(y, h, l);
        ohi[base + c] = h;
        olo[base + c] = l;
    }
}

// ---------------- GEMM: BK=32, 3-stage cp.async, 2 CTAs/SM ----------------------
#define STG32      8192            // one 128x32 bf16 tile
#define STAGE32    (4 * STG32)     // Ah, Al, Bh, Bl
#define GEMM_SMEM  (3 * STAGE32)   // 98304

__device__ __forceinline__ void cp_tile32(const char* src, int ldbytes,
                                          uint32_t dst, int tid)
{
    #pragma unroll
    for (int i = 0; i < 2; i++) {
        int idx = tid + i * 256;
        int r = idx >> 2, c = idx & 3;
        cp16(dst + sw128b((r << 6) + (c << 4)), src + (size_t)r * ldbytes + c * 16);
    }
}

__device__ __forceinline__ void compute_stage32(uint32_t sb, int m0, int n0,
                                                int lane, float acc[4][4][4])
{
    uint32_t aAh = sb, aAl = sb + STG32, aBh = sb + 2 * STG32, aBl = sb + 3 * STG32;
    #pragma unroll
    for (int k16 = 0; k16 < 2; k16++) {
        uint32_t ah[4][4], al[4][4], bh[2][4], bl[2][4];
        #pragma unroll
        for (int mi = 0; mi < 4; mi++) {
            ldsm4(frag_a32(aAh, m0 + mi * 16, k16, lane), ah[mi]);
            ldsm4(frag_a32(aAl, m0 + mi * 16, k16, lane), al[mi]);
        }
        #pragma unroll
        for (int g = 0; g < 2; g++) {
            ldsm4(frag_a32(aBh, n0 + g * 16, k16, lane), bh[g]);
            ldsm4(frag_a32(aBl, n0 + g * 16, k16, lane), bl[g]);
        }
        #pragma unroll
        for (int mi = 0; mi < 4; mi++) {
            #pragma unroll
            for (int g = 0; g < 2; g++) {
                mma16816(acc[mi][g * 2 + 0], ah[mi], bh[g][0], bh[g][2]);
                mma16816(acc[mi][g * 2 + 1], ah[mi], bh[g][1], bh[g][3]);
                mma16816(acc[mi][g * 2 + 0], ah[mi], bl[g][0], bl[g][2]);
                mma16816(acc[mi][g * 2 + 1], ah[mi], bl[g][1], bl[g][3]);
                mma16816(acc[mi][g * 2 + 0], al[mi], bh[g][0], bh[g][2]);
                mma16816(acc[mi][g * 2 + 1], al[mi], bh[g][1], bh[g][3]);
            }
        }
    }
}

// EPI: 1=bias+gelu->bf16 hi/lo, 2=bias+residual->f32, 3=bias->bf16 hi/lo
template <int EPI>
__global__ void __launch_bounds__(256, 2) mma_gemm(
    const __nv_bfloat16* __restrict__ Ahi, const __nv_bfloat16* __restrict__ Alo,
    const __nv_bfloat16* __restrict__ Bhi, const __nv_bfloat16* __restrict__ Blo,
    const float* __restrict__ bias, const float* __restrict__ R,
    float* __restrict__ Cf, __nv_bfloat16* __restrict__ Chi,
    __nv_bfloat16* __restrict__ Clo, int M, int N, int K)
{
    extern __shared__ __align__(128) char sm[];
    uint32_t smb = smem_u32(sm);
    int tid = threadIdx.x, lane = tid & 31, wid = tid >> 5;
    int bm = blockIdx.y * 128, bn = blockIdx.x * 128;
    int m0 = (wid & 1) * 64, n0 = (wid >> 1) * 32;

    const char* Ah = (const char*)(Ahi + (size_t)bm * K);
    const char* Al = (const char*)(Alo + (size_t)bm * K);
    const char* Bh = (const char*)(Bhi + (size_t)bn * K);
    const char* Bl = (const char*)(Blo + (size_t)bn * K);
    int ldb = K * 2;

    float acc[4][4][4];
    #pragma unroll
    for (int a = 0; a < 4; a++)
        #pragma unroll
        for (int b = 0; b < 4; b++)
            #pragma unroll
            for (int c = 0; c < 4; c++) acc[a][b][c] = 0.f;

    int KT = K >> 5;

    #pragma unroll
    for (int s = 0; s < 2; s++) {
        uint32_t st = smb + s * STAGE32;
        cp_tile32(Ah + s * 64, ldb, st,             tid);
        cp_tile32(Al + s * 64, ldb, st +     STG32, tid);
        cp_tile32(Bh + s * 64, ldb, st + 2 * STG32, tid);
        cp_tile32(Bl + s * 64, ldb, st + 3 * STG32, tid);
        CP_COMMIT();
    }

    for (int kt = 0; kt < KT; kt++) {
        if (kt + 2 < KT) {
            uint32_t st = smb + ((kt + 2) % 3) * STAGE32;
            cp_tile32(Ah + (size_t)(kt + 2) * 64, ldb, st,             tid);
            cp_tile32(Al + (size_t)(kt + 2) * 64, ldb, st +     STG32, tid);
            cp_tile32(Bh + (size_t)(kt + 2) * 64, ldb, st + 2 * STG32, tid);
            cp_tile32(Bl + (size_t)(kt + 2) * 64, ldb, st + 3 * STG32, tid);
            CP_COMMIT();
        }
        int rem = KT - 1 - kt;
        if (rem >= 2) CP_WAIT_2(); else if (rem == 1) CP_WAIT_1(); else CP_WAIT_0();
        __syncthreads();
        compute_stage32(smb + (kt % 3) * STAGE32, m0, n0, lane, acc);
        __syncthreads();
    }

    int r_lo = lane >> 2;
    int c2   = (lane & 3) << 1;
    #pragma unroll
    for (int mi = 0; mi < 4; mi++) {
        #pragma unroll
        for (int nj = 0; nj < 4; nj++) {
            int gr = bm + m0 + mi * 16 + r_lo;
            int gc = bn + n0 + nj * 8 + c2;
            float2 bv = *(const float2*)&bias[gc];
            float v0 = acc[mi][nj][0] + bv.x;
            float v1 = acc[mi][nj][1] + bv.y;
            float v2 = acc[mi][nj][2] + bv.x;
            float v3 = acc[mi][nj][3] + bv.y;
            size_t go0 = (size_t)gr * N + gc;
            size_t go1 = (size_t)(gr + 8) * N + gc;
            if (EPI == 2) {
                float2 r0 = *(const float2*)&R[go0];
                float2 r1 = *(const float2*)&R[go1];
                *(float2*)&Cf[go0] = make_float2(v0 + r0.x, v1 + r0.y);
                *(float2*)&Cf[go1] = make_float2(v2 + r1.x, v3 + r1.y);
            } else {
                if (EPI == 1) {
                    v0 = gelu_f(v0); v1 = gelu_f(v1);
                    v2 = gelu_f(v2); v3 = gelu_f(v3);
                }
                __nv_bfloat16 h0,l0,h1,l1,h2,l2,h3,l3;
                split_bf16(v0,h0,l0); split_bf16(v1,h1,l1);
                split_bf16(v2,h2,l2); split_bf16(v3,h3,l3);
                *(__nv_bfloat162*)&Chi[go0] = __halves2bfloat162(h0, h1);
                *(__nv_bfloat162*)&Clo[go0] = __halves2bfloat162(l0, l1);
                *(__nv_bfloat162*)&Chi[go1] = __halves2bfloat162(h2, h3);
                *(__nv_bfloat162*)&Clo[go1] = __halves2bfloat162(l2, l3);
            }
        }
    }
}

// ---------------- Attention: mma.sync flash, hi/lo split ------------------------
// CTA = 64 queries x 1 head x 1 batch. 128 threads (4 warps x 16 query rows).
// smem: Qh(8K) Ql(8K), 2 stages of {Kh,Kl,Vh,Vl} (32K each) = 80KB.
#define ATT_SMEM (16384 + 2 * 32768)

__global__ void __launch_bounds__(128) attn_mma(
    const __nv_bfloat16* __restrict__ qh, const __nv_bfloat16* __restrict__ ql,
    __nv_bfloat16* __restrict__ chi, __nv_bfloat16* __restrict__ clo)
{
    extern __shared__ __align__(128) char sm[];
    uint32_t smb = smem_u32(sm);
    int tid = threadIdx.x, lane = tid & 31, wid = tid >> 5;
    int qt = blockIdx.x, h = blockIdx.y, bb = blockIdx.z;
    int row0 = bb * SEQ + qt * 64;
    int mrow = wid * 16;

    const int ldq = C3 * 2;   // bytes per token row
    const char* qbh = (const char*)(qh + (size_t)row0 * C3 + h * 64);
    const char* qbl = (const char*)(ql + (size_t)row0 * C3 + h * 64);

    uint32_t sQh = smb, sQl = smb + 8192;

    // Q tile: 64 rows x 128B, both tensors
    #pragma unroll
    for (int i = 0; i < 4; i++) {
        int idx = tid + i * 128;
        int r = idx >> 3, c = idx & 7;
        uint32_t off = sw128b((r << 7) + (c << 4));
        cp16(sQh + off, qbh + (size_t)r * ldq + c * 16);
        cp16(sQl + off, qbl + (size_t)r * ldq + c * 16);
    }
    // KV tile 0
    {
        int kr = bb * SEQ;
        const char* kbh = (const char*)(qh + (size_t)kr * C3 + EMBED + h * 64);
        const char* kbl = (const char*)(ql + (size_t)kr * C3 + EMBED + h * 64);
        const char* vbh = (const char*)(qh + (size_t)kr * C3 + 2 * EMBED + h * 64);
        const char* vbl = (const char*)(ql + (size_t)kr * C3 + 2 * EMBED + h * 64);
        uint32_t st = smb + 16384;
        #pragma unroll
        for (int i = 0; i < 4; i++) {
            int idx = tid + i * 128;
            int r = idx >> 3, c = idx & 7;
            uint32_t off = sw128b((r << 7) + (c << 4));
            size_t gsrc = (size_t)r * ldq + c * 16;
            cp16(st + off,          kbh + gsrc);
            cp16(st +  8192 + off,  kbl + gsrc);
            cp16(st + 16384 + off,  vbh + gsrc);
            cp16(st + 24576 + off,  vbl + gsrc);
        }
    }
    CP_COMMIT();

    float m0 = -1e30f, m1 = -1e30f, l0 = 0.f, l1 = 0.f;
    float oacc[8][4];
    #pragma unroll
    for (int j = 0; j < 8; j++)
        #pragma unroll
        for (int e = 0; e < 4; e++) oacc[j][e] = 0.f;

    uint32_t qfh[4][4], qfl[4][4];

    const int NT = SEQ / 64;
    for (int kt = 0; kt < NT; kt++) {
        if (kt + 1 < NT) {
            int kr = bb * SEQ + (kt + 1) * 64;
            const char* kbh = (const char*)(qh + (size_t)kr * C3 + EMBED + h * 64);
            const char* kbl = (const char*)(ql + (size_t)kr * C3 + EMBED + h * 64);
            const char* vbh = (const char*)(qh + (size_t)kr * C3 + 2 * EMBED + h * 64);
            const char* vbl = (const char*)(ql + (size_t)kr * C3 + 2 * EMBED + h * 64);
            uint32_t st = smb + 16384 + ((kt + 1) & 1) * 32768;
            #pragma unroll
            for (int i = 0; i < 4; i++) {
                int idx = tid + i * 128;
                int r = idx >> 3, c = idx & 7;
                uint32_t off = sw128b((r << 7) + (c << 4));
                size_t gsrc = (size_t)r * ldq + c * 16;
                cp16(st + off,          kbh + gsrc);
                cp16(st +  8192 + off,  kbl + gsrc);
                cp16(st + 16384 + off,  vbh + gsrc);
                cp16(st + 24576 + off,  vbl + gsrc);
            }
            CP_COMMIT();
            CP_WAIT_1();
        } else {
            CP_WAIT_0();
        }
        __syncthreads();

        if (kt == 0) {
            #pragma unroll
            for (int k16 = 0; k16 < 4; k16++) {
                ldsm4(frag_addr(sQh, mrow, k16, lane), qfh[k16]);
                ldsm4(frag_addr(sQl, mrow, k16, lane), qfl[k16]);
            }
        }

        uint32_t st  = smb + 16384 + (kt & 1) * 32768;
        uint32_t sKh = st, sKl = st + 8192, sVh = st + 16384, sVl = st + 24576;

        // ---- S = Q K^T (3 terms) ----
        float sacc[8][4];
        #pragma unroll
        for (int j = 0; j < 8; j++)
            #pragma unroll
            for (int e = 0; e < 4; e++) sacc[j][e] = 0.f;

        #pragma unroll
        for (int k16 = 0; k16 < 4; k16++) {
            #pragma unroll
            for (int g = 0; g < 4; g++) {
                uint32_t kh[4], kl[4];
                ldsm4(frag_addr(sKh, g * 16, k16, lane), kh);
                ldsm4(frag_addr(sKl, g * 16, k16, lane), kl);
                mma16816(sacc[g * 2 + 0], qfh[k16], kh[0], kh[2]);
                mma16816(sacc[g * 2 + 1], qfh[k16], kh[1], kh[3]);
                mma16816(sacc[g * 2 + 0], qfh[k16], kl[0], kl[2]);
                mma16816(sacc[g * 2 + 1], qfh[k16], kl[1], kl[3]);
                mma16816(sacc[g * 2 + 0], qfl[k16], kh[0], kh[2]);
                mma16816(sacc[g * 2 + 1], qfl[k16], kh[1], kh[3]);
            }
        }

        // ---- online softmax ----
        #pragma unroll
        for (int j = 0; j < 8; j++)
            #pragma unroll
            for (int e = 0; e < 4; e++) sacc[j][e] *= 0.125f;

        float mx0 = -1e30f, mx1 = -1e30f;
        #pragma unroll
        for (int j = 0; j < 8; j++) {
            mx0 = fmaxf(mx0, fmaxf(sacc[j][0], sacc[j][1]));
            mx1 = fmaxf(mx1, fmaxf(sacc[j][2], sacc[j][3]));
        }
        mx0 = fmaxf(mx0, __shfl_xor_sync(0xffffffffu, mx0, 1));
        mx0 = fmaxf(mx0, __shfl_xor_sync(0xffffffffu, mx0, 2));
        mx1 = fmaxf(mx1, __shfl_xor_sync(0xffffffffu, mx1, 1));
        mx1 = fmaxf(mx1, __shfl_xor_sync(0xffffffffu, mx1, 2));
        float mn0 = fmaxf(m0, mx0), mn1 = fmaxf(m1, mx1);
        float c0 = __expf(m0 - mn0), c1 = __expf(m1 - mn1);
        m0 = mn0; m1 = mn1;

        float s0 = 0.f, s1 = 0.f;
        #pragma unroll
        for (int j = 0; j < 8; j++) {
            sacc[j][0] = __expf(sacc[j][0] - mn0); s0 += sacc[j][0];
            sacc[j][1] = __expf(sacc[j][1] - mn0); s0 += sacc[j][1];
            sacc[j][2] = __expf(sacc[j][2] - mn1); s1 += sacc[j][2];
            sacc[j][3] = __expf(sacc[j][3] - mn1); s1 += sacc[j][3];
        }
        s0 += __shfl_xor_sync(0xffffffffu, s0, 1);
        s0 += __shfl_xor_sync(0xffffffffu, s0, 2);
        s1 += __shfl_xor_sync(0xffffffffu, s1, 1);
        s1 += __shfl_xor_sync(0xffffffffu, s1, 2);
        l0 = l0 * c0 + s0;
        l1 = l1 * c1 + s1;
        #pragma unroll
        for (int j = 0; j < 8; j++) {
            oacc[j][0] *= c0; oacc[j][1] *= c0;
            oacc[j][2] *= c1; oacc[j][3] *= c1;
        }

        // ---- O += P V (3 terms), A-frags from sacc, B via ldmatrix.trans ----
        #pragma unroll
        for (int t = 0; t < 4; t++) {
            uint32_t ph[4], pl[4];
            #pragma unroll
            for (int q = 0; q < 4; q++) {
                int blk = 2 * t + (q >> 1);
                int e0  = (q & 1) * 2;
                float x = sacc[blk][e0], y = sacc[blk][e0 + 1];
                __nv_bfloat16 hx, lx, hy, ly;
                split_bf16(x, hx, lx); split_bf16(y, hy, ly);
                __nv_bfloat162 hh = __halves2bfloat162(hx, hy);
                __nv_bfloat162 ll = __halves2bfloat162(lx, ly);
                ph[q] = *(uint32_t*)&hh;
                pl[q] = *(uint32_t*)&ll;
            }
            // A-frag order: a0=(r,k0-7), a1=(r+8,k0-7), a2=(r,k8-15), a3=(r+8,k8-15)
            uint32_t pa_h[4] = { ph[0], ph[1], ph[2], ph[3] };
            uint32_t pa_l[4] = { pl[0], pl[1], pl[2], pl[3] };
            #pragma unroll
            for (int g16 = 0; g16 < 4; g16++) {
                uint32_t vh[4], vl[4];
                ldsm4t(vaddr(sVh, t * 16, g16 * 16, lane), vh);
                ldsm4t(vaddr(sVl, t * 16, g16 * 16, lane), vl);
                mma16816(oacc[g16 * 2 + 0], pa_h, vh[0], vh[2]);
                mma16816(oacc[g16 * 2 + 1], pa_h, vh[1], vh[3]);
                mma16816(oacc[g16 * 2 + 0], pa_h, vl[0], vl[2]);
                mma16816(oacc[g16 * 2 + 1], pa_h, vl[1], vl[3]);
                mma16816(oacc[g16 * 2 + 0], pa_l, vh[0], vh[2]);
                mma16816(oacc[g16 * 2 + 1], pa_l, vh[1], vh[3]);
            }
        }
        __syncthreads();
    }

    // ---- write ctx (bf16 hi/lo) ----
    float inv0 = 1.0f / l0, inv1 = 1.0f / l1;
    int r = lane >> 2;
    int c2 = (lane & 3) << 1;
    #pragma unroll
    for (int j = 0; j < 8; j++) {
        int col = h * 64 + j * 8 + c2;
        size_t go0 = (size_t)(row0 + mrow + r) * EMBED + col;
        size_t go1 = (size_t)(row0 + mrow + r + 8) * EMBED + col;
        float v0 = oacc[j][0] * inv0, v1 = oacc[j][1] * inv0;
        float v2 = oacc[j][2] * inv1, v3 = oacc[j][3] * inv1;
        __nv_bfloat16 h0,l0b,h1,l1b,h2,l2b,h3,l3b;
        split_bf16(v0,h0,l0b); split_bf16(v1,h1,l1b);
        split_bf16(v2,h2,l2b); split_bf16(v3,h3,l3b);
        *(__nv_bfloat162*)&chi[go0] = __halves2bfloat162(h0, h1);
        *(__nv_bfloat162*)&clo[go0] = __halves2bfloat162(l0b, l1b);
        *(__nv_bfloat162*)&chi[go1] = __halves2bfloat162(h2, h3);
        *(__nv_bfloat162*)&clo[go1] = __halves2bfloat162(l2b, l3b);
    }
}

// ---------------- launch ---------------------------------------------------------
extern "C" void kernel_launch(void* const* d_in, const int* in_sizes, int n_in,
                              void* d_out, int out_size)
{
    const float* x      = (const float*)d_in[0];
    const float* ln1_g  = (const float*)d_in[1];
    const float* ln1_b  = (const float*)d_in[2];
    const float* qkv_w  = (const float*)d_in[3];
    const float* qkv_b  = (const float*)d_in[4];
    const float* proj_w = (const float*)d_in[5];
    const float* proj_b = (const float*)d_in[6];
    const float* ln2_g  = (const float*)d_in[7];
    const float* ln2_b  = (const float*)d_in[8];
    const float* fc1_w  = (const float*)d_in[9];
    const float* fc1_b  = (const float*)d_in[10];
    const float* fc2_w  = (const float*)d_in[11];
    const float* fc2_b  = (const float*)d_in[12];
    float* out = (float*)d_out;

    float *x1;
    __nv_bfloat16 *qkvh, *qkvl, *hhi, *hlo, *chi, *clo, *fhi, *flo;
    __nv_bfloat16 *w0h, *w0l, *w1h, *w1l, *w2h, *w2l, *w3h, *w3l;
    cudaGetSymbolAddress((void**)&x1,   g_x1);
    cudaGetSymbolAddress((void**)&qkvh, g_qkvh); cudaGetSymbolAddress((void**)&qkvl, g_qkvl);
    cudaGetSymbolAddress((void**)&hhi,  g_hhi);  cudaGetSymbolAddress((void**)&hlo, g_hlo);
    cudaGetSymbolAddress((void**)&chi,  g_chi);  cudaGetSymbolAddress((void**)&clo, g_clo);
    cudaGetSymbolAddress((void**)&fhi,  g_fhi);  cudaGetSymbolAddress((void**)&flo, g_flo);
    cudaGetSymbolAddress((void**)&w0h,  g_w0h);  cudaGetSymbolAddress((void**)&w0l, g_w0l);
    cudaGetSymbolAddress((void**)&w1h,  g_w1h);  cudaGetSymbolAddress((void**)&w1l, g_w1l);
    cudaGetSymbolAddress((void**)&w2h,  g_w2h);  cudaGetSymbolAddress((void**)&w2l, g_w2l);
    cudaGetSymbolAddress((void**)&w3h,  g_w3h);  cudaGetSymbolAddress((void**)&w3l, g_w3l);

    cudaFuncSetAttribute(attn_mma,    cudaFuncAttributeMaxDynamicSharedMemorySize, ATT_SMEM);
    cudaFuncSetAttribute(mma_gemm<1>, cudaFuncAttributeMaxDynamicSharedMemorySize, GEMM_SMEM);
    cudaFuncSetAttribute(mma_gemm<2>, cudaFuncAttributeMaxDynamicSharedMemorySize, GEMM_SMEM);
    cudaFuncSetAttribute(mma_gemm<3>, cudaFuncAttributeMaxDynamicSharedMemorySize, GEMM_SMEM);

    transpose_split<<<dim3(C3 / 32,    EMBED / 32), 256>>>(qkv_w,  w0h, w0l, EMBED, C3);
    transpose_split<<<dim3(EMBED / 32, EMBED / 32), 256>>>(proj_w, w1h, w1l, EMBED, EMBED);
    transpose_split<<<dim3(HID / 32,   EMBED / 32), 256>>>(fc1_w,  w2h, w2l, EMBED, HID);
    transpose_split<<<dim3(EMBED / 32, HID / 32),   256>>>(fc2_w,  w3h, w3l, HID, EMBED);

    ln_kernel<<<TOK, 256>>>(x, ln1_g, ln1_b, hhi, hlo);
    mma_gemm<3><<<dim3(C3 / 128, TOK / 128), 256, GEMM_SMEM>>>(
        hhi, hlo, w0h, w0l, qkv_b, nullptr, nullptr, qkvh, qkvl,
        TOK, C3, EMBED);
    attn_mma<<<dim3(SEQ / 64, NHEAD, 2), 128, ATT_SMEM>>>(qkvh, qkvl, chi, clo);
    mma_gemm<2><<<dim3(EMBED / 128, TOK / 128), 256, GEMM_SMEM>>>(
        chi, clo, w1h, w1l, proj_b, x, x1, nullptr, nullptr,
        TOK, EMBED, EMBED);
    ln_kernel<<<TOK, 256>>>(x1, ln2_g, ln2_b, hhi, hlo);
    mma_gemm<1><<<dim3(HID / 128, TOK / 128), 256, GEMM_SMEM>>>(
        hhi, hlo, w2h, w2l, fc1_b, nullptr, nullptr, fhi, flo,
        TOK, HID, EMBED);
    mma_gemm<2><<<dim3(EMBED / 128, TOK / 128), 256, GEMM_SMEM>>>(
        fhi, flo, w3h, w3l, fc2_b, x1, out, nullptr, nullptr,
        TOK, EMBED, HID);
}